// round 1
// baseline (speedup 1.0000x reference)
#include <cuda_runtime.h>

#define BATCH 8
#define SEQ   1024
#define DIM   768
#define NHEAD 12
#define HDIM  64
#define BH    (BATCH * NHEAD)     // 96
#define MROWS (BATCH * SEQ)       // 8192
#define OUT_OFF ((size_t)MROWS * DIM)  // 6291456 floats: out, then weights

// Scratch (alloc-free rule: __device__ globals). 4 x 25MB.
__device__ float g_Q[BH * SEQ * HDIM];
__device__ float g_K[BH * SEQ * HDIM];
__device__ float g_V[BH * SEQ * HDIM];
__device__ float g_O[BH * SEQ * HDIM];

// ---------------------------------------------------------------------------
// Kernel 1: QKV projection. C = X @ W + b, output stored head-split
// [B, H, N, D].  M=8192, N=768, K=768.  64x64 tile, 4x4 microtile.
// sel: 0->g_Q, 1->g_K, 2->g_V
// ---------------------------------------------------------------------------
__global__ void proj_headsplit(const float* __restrict__ X,
                               const float* __restrict__ W,
                               const float* __restrict__ bias, int sel) {
    __shared__ float As[64][17];
    __shared__ float Bs[16][64];
    float* Out = (sel == 0) ? g_Q : (sel == 1) ? g_K : g_V;

    int tid = threadIdx.x;
    int tx = tid & 15, ty = tid >> 4;
    int row0 = blockIdx.y * 64;
    int col0 = blockIdx.x * 64;

    float acc[4][4] = {};
    for (int k0 = 0; k0 < DIM; k0 += 16) {
        #pragma unroll
        for (int i = tid; i < 64 * 16; i += 256) {
            int r = i >> 4, c = i & 15;
            As[r][c] = X[(size_t)(row0 + r) * DIM + k0 + c];
        }
        #pragma unroll
        for (int i = tid; i < 16 * 64; i += 256) {
            int r = i >> 6, c = i & 63;
            Bs[r][c] = W[(size_t)(k0 + r) * DIM + col0 + c];
        }
        __syncthreads();
        #pragma unroll
        for (int kk = 0; kk < 16; ++kk) {
            float a[4], b[4];
            #pragma unroll
            for (int u = 0; u < 4; ++u) a[u] = As[ty * 4 + u][kk];
            #pragma unroll
            for (int v = 0; v < 4; ++v) b[v] = Bs[kk][tx * 4 + v];
            #pragma unroll
            for (int u = 0; u < 4; ++u)
                #pragma unroll
                for (int v = 0; v < 4; ++v) acc[u][v] += a[u] * b[v];
        }
        __syncthreads();
    }
    #pragma unroll
    for (int u = 0; u < 4; ++u) {
        int r = row0 + ty * 4 + u;          // b*1024 + n
        int b = r >> 10, n = r & 1023;
        #pragma unroll
        for (int v = 0; v < 4; ++v) {
            int c = col0 + tx * 4 + v;      // h*64 + d
            int h = c >> 6, d = c & 63;
            Out[(((size_t)(b * NHEAD + h) * SEQ + n) * HDIM) + d] =
                acc[u][v] + bias[c];
        }
    }
}

// ---------------------------------------------------------------------------
// Kernel 2: scores = scale * Q @ K^T per (b,h).  Writes directly into the
// weights region of d_out.  Per bh: M=N=1024, K=64 (fully in smem).
// ---------------------------------------------------------------------------
__global__ void scores_kernel(float* __restrict__ Wt) {
    __shared__ float Qs[64][65];
    __shared__ float Ks[64][65];
    int bh = blockIdx.z;
    int tid = threadIdx.x;
    int tx = tid & 15, ty = tid >> 4;
    int i0 = blockIdx.y * 64;
    int j0 = blockIdx.x * 64;
    const float* Qb = g_Q + (size_t)bh * SEQ * HDIM;
    const float* Kb = g_K + (size_t)bh * SEQ * HDIM;

    #pragma unroll
    for (int i = tid; i < 64 * 64; i += 256) {
        int r = i >> 6, c = i & 63;
        Qs[r][c] = Qb[(size_t)(i0 + r) * HDIM + c];
        Ks[r][c] = Kb[(size_t)(j0 + r) * HDIM + c];
    }
    __syncthreads();

    float acc[4][4] = {};
    #pragma unroll 16
    for (int kk = 0; kk < 64; ++kk) {
        float a[4], b[4];
        #pragma unroll
        for (int u = 0; u < 4; ++u) a[u] = Qs[ty * 4 + u][kk];
        #pragma unroll
        for (int v = 0; v < 4; ++v) b[v] = Ks[tx * 4 + v][kk];
        #pragma unroll
        for (int u = 0; u < 4; ++u)
            #pragma unroll
            for (int v = 0; v < 4; ++v) acc[u][v] += a[u] * b[v];
    }
    const float scale = 0.125f;   // 1/sqrt(64)
    #pragma unroll
    for (int u = 0; u < 4; ++u) {
        size_t rbase = ((size_t)bh * SEQ + i0 + ty * 4 + u) * SEQ;
        #pragma unroll
        for (int v = 0; v < 4; ++v)
            Wt[rbase + j0 + tx * 4 + v] = acc[u][v] * scale;
    }
}

// ---------------------------------------------------------------------------
// Kernel 3: in-place row softmax over the weights. One block per row (1024).
// ---------------------------------------------------------------------------
__global__ void softmax_kernel(float* __restrict__ Wt) {
    int row = blockIdx.x;                 // 0 .. BH*SEQ-1
    float* p = Wt + (size_t)row * SEQ;
    int tid = threadIdx.x;                // 256 threads, 4 elems each
    float4 v = reinterpret_cast<float4*>(p)[tid];

    __shared__ float red[8];
    float m = fmaxf(fmaxf(v.x, v.y), fmaxf(v.z, v.w));
    #pragma unroll
    for (int o = 16; o; o >>= 1) m = fmaxf(m, __shfl_xor_sync(~0u, m, o));
    if ((tid & 31) == 0) red[tid >> 5] = m;
    __syncthreads();
    m = red[0];
    #pragma unroll
    for (int i = 1; i < 8; ++i) m = fmaxf(m, red[i]);
    __syncthreads();

    v.x = __expf(v.x - m); v.y = __expf(v.y - m);
    v.z = __expf(v.z - m); v.w = __expf(v.w - m);
    float s = v.x + v.y + v.z + v.w;
    #pragma unroll
    for (int o = 16; o; o >>= 1) s += __shfl_xor_sync(~0u, s, o);
    if ((tid & 31) == 0) red[tid >> 5] = s;
    __syncthreads();
    s = red[0];
    #pragma unroll
    for (int i = 1; i < 8; ++i) s += red[i];

    float inv = 1.0f / s;
    v.x *= inv; v.y *= inv; v.z *= inv; v.w *= inv;
    reinterpret_cast<float4*>(p)[tid] = v;
}

// ---------------------------------------------------------------------------
// Kernel 4: O = attn @ V per (b,h).  M=1024, N=64, K=1024.
// ---------------------------------------------------------------------------
__global__ void av_kernel(const float* __restrict__ Wt) {
    __shared__ float As[64][17];
    __shared__ float Bs[16][64];
    int bh = blockIdx.z;
    int i0 = blockIdx.y * 64;
    int tid = threadIdx.x;
    int tx = tid & 15, ty = tid >> 4;
    const float* A = Wt + (size_t)bh * SEQ * SEQ;
    const float* Vb = g_V + (size_t)bh * SEQ * HDIM;

    float acc[4][4] = {};
    for (int k0 = 0; k0 < SEQ; k0 += 16) {
        #pragma unroll
        for (int i = tid; i < 64 * 16; i += 256) {
            int r = i >> 4, c = i & 15;
            As[r][c] = A[(size_t)(i0 + r) * SEQ + k0 + c];
        }
        #pragma unroll
        for (int i = tid; i < 16 * 64; i += 256) {
            int r = i >> 6, c = i & 63;
            Bs[r][c] = Vb[(size_t)(k0 + r) * HDIM + c];
        }
        __syncthreads();
        #pragma unroll
        for (int kk = 0; kk < 16; ++kk) {
            float a[4], b[4];
            #pragma unroll
            for (int u = 0; u < 4; ++u) a[u] = As[ty * 4 + u][kk];
            #pragma unroll
            for (int v = 0; v < 4; ++v) b[v] = Bs[kk][tx * 4 + v];
            #pragma unroll
            for (int u = 0; u < 4; ++u)
                #pragma unroll
                for (int v = 0; v < 4; ++v) acc[u][v] += a[u] * b[v];
        }
        __syncthreads();
    }
    #pragma unroll
    for (int u = 0; u < 4; ++u)
        #pragma unroll
        for (int v = 0; v < 4; ++v)
            g_O[((size_t)bh * SEQ + i0 + ty * 4 + u) * HDIM + tx * 4 + v] =
                acc[u][v];
}

// ---------------------------------------------------------------------------
// Kernel 5: out = merge_heads(O) @ Wo + bo.  Gather from head-split layout
// during the A-tile load.  M=8192, N=768, K=768.
// ---------------------------------------------------------------------------
__global__ void out_proj(const float* __restrict__ Wo,
                         const float* __restrict__ bo,
                         float* __restrict__ Out) {
    __shared__ float As[64][17];
    __shared__ float Bs[16][64];
    int tid = threadIdx.x;
    int tx = tid & 15, ty = tid >> 4;
    int row0 = blockIdx.y * 64;
    int col0 = blockIdx.x * 64;

    float acc[4][4] = {};
    for (int k0 = 0; k0 < DIM; k0 += 16) {
        #pragma unroll
        for (int i = tid; i < 64 * 16; i += 256) {
            int r = i >> 4, c = i & 15;
            int gr = row0 + r;                  // b*1024 + n
            int b = gr >> 10, n = gr & 1023;
            int k = k0 + c;                     // h*64 + d
            As[r][c] =
                g_O[((size_t)(b * NHEAD + (k >> 6)) * SEQ + n) * HDIM + (k & 63)];
        }
        #pragma unroll
        for (int i = tid; i < 16 * 64; i += 256) {
            int r = i >> 6, c = i & 63;
            Bs[r][c] = Wo[(size_t)(k0 + r) * DIM + col0 + c];
        }
        __syncthreads();
        #pragma unroll
        for (int kk = 0; kk < 16; ++kk) {
            float a[4], b[4];
            #pragma unroll
            for (int u = 0; u < 4; ++u) a[u] = As[ty * 4 + u][kk];
            #pragma unroll
            for (int v = 0; v < 4; ++v) b[v] = Bs[kk][tx * 4 + v];
            #pragma unroll
            for (int u = 0; u < 4; ++u)
                #pragma unroll
                for (int v = 0; v < 4; ++v) acc[u][v] += a[u] * b[v];
        }
        __syncthreads();
    }
    #pragma unroll
    for (int u = 0; u < 4; ++u) {
        int r = row0 + ty * 4 + u;
        #pragma unroll
        for (int v = 0; v < 4; ++v) {
            int c = col0 + tx * 4 + v;
            Out[(size_t)r * DIM + c] = acc[u][v] + bo[c];
        }
    }
}

// ---------------------------------------------------------------------------
extern "C" void kernel_launch(void* const* d_in, const int* in_sizes, int n_in,
                              void* d_out, int out_size) {
    const float* x  = (const float*)d_in[0];
    const float* Wq = (const float*)d_in[1];
    const float* bq = (const float*)d_in[2];
    const float* Wk = (const float*)d_in[3];
    const float* bk = (const float*)d_in[4];
    const float* Wv = (const float*)d_in[5];
    const float* bv = (const float*)d_in[6];
    const float* Wo = (const float*)d_in[7];
    const float* bo = (const float*)d_in[8];

    float* out = (float*)d_out;             // [8,1024,768]
    float* wts = out + OUT_OFF;             // [8,12,1024,1024]

    dim3 gProj(DIM / 64, MROWS / 64);       // (12, 128)
    proj_headsplit<<<gProj, 256>>>(x, Wq, bq, 0);
    proj_headsplit<<<gProj, 256>>>(x, Wk, bk, 1);
    proj_headsplit<<<gProj, 256>>>(x, Wv, bv, 2);

    scores_kernel<<<dim3(SEQ / 64, SEQ / 64, BH), 256>>>(wts);   // (16,16,96)
    softmax_kernel<<<BH * SEQ, 256>>>(wts);                      // 98304 rows
    av_kernel<<<dim3(1, SEQ / 64, BH), 256>>>(wts);              // (1,16,96)
    out_proj<<<gProj, 256>>>(Wo, bo, out);
}